// round 14
// baseline (speedup 1.0000x reference)
#include <cuda_runtime.h>
#include <cuda_fp16.h>

#define DINLINE __device__ __forceinline__
typedef unsigned int u32;
typedef unsigned short u16;

constexpr int B_ = 8, T_ = 64, N_ = 512, H_ = 128, E_ = 8192;
constexpr int S_ = B_ * N_;       // 4096 sequences
constexpr int G1_ = 128, G2_ = 64;
constexpr int G4H = 4 * H_;       // 512 gate rows

// ---------------- SMEM layout (byte offsets) -----------------------------------
constexpr int WROW    = 272;                   // 136 fp16 per row (128 + 8 pad)
constexpr int OFF_W   = 0;                     // 512*272 = 139264
constexpr int OFF_H   = 139264;                // h planes (2 x 32 x 272), fp16
constexpr int HPLANE  = 32 * WROW;             // 8704
constexpr int OFF_SX  = OFF_H + 2 * HPLANE;    // 156672 (MODE 0 only): 8192 B
constexpr int REC_SM  = OFF_SX + 8192;         // 164864

constexpr int OFF_AH  = 139264;                // proj: A plane 128*272
constexpr int APLANE  = 128 * WROW;            // 34816
constexpr int PROJ_SM = OFF_AH + APLANE;       // 174080

// ---------------- device scratch (static globals; no allocation) ---------------
__device__ __half g_hh [(size_t)T_ * S_ * H_];   // [t*S+s][j]    64 MiB
__device__ __half g_xph[(size_t)T_ * S_ * G4H];  // [t*S+s][4j+g] 256 MiB
__device__ u32   g_whh_h[3][G4H * 64];           // permuted fp16-pair W_hh
__device__ u32   g_wih_h[2][G4H * 64];           // permuted fp16-pair W_ih
__device__ float g_br[3][G4H];                   // b_ih+b_hh permuted (4j+g)
__device__ float g_w0r[G4H];                     // w_ih0 permuted
__device__ float g_xl1[S_ * G1_];
__device__ float g_h1[S_ * G1_];
__device__ float g_xl2[S_ * G2_];
__device__ float g_h2[S_ * G2_];
__device__ float g_dis[N_];
__device__ int   g_is64;

// ---------------- helpers -------------------------------------------------------
DINLINE float tanhfast(float x) {
    float y;
    asm("tanh.approx.f32 %0, %1;" : "=f"(y) : "f"(x));
    return y;
}

DINLINE u32 smem_u32(const void* p) {
    u32 a;
    asm("{ .reg .u64 t; cvta.to.shared.u64 t, %1; cvt.u32.u64 %0, t; }" : "=r"(a) : "l"(p));
    return a;
}

DINLINE void mma_f16(float* D, const u32* A, u32 b0, u32 b1) {
    asm("mma.sync.aligned.m16n8k16.row.col.f32.f16.f16.f32 "
        "{%0,%1,%2,%3},{%4,%5,%6,%7},{%8,%9},{%0,%1,%2,%3};"
        : "+f"(D[0]), "+f"(D[1]), "+f"(D[2]), "+f"(D[3])
        : "r"(A[0]), "r"(A[1]), "r"(A[2]), "r"(A[3]), "r"(b0), "r"(b1));
}

#define LDSM4(R, ADDR) \
    asm volatile("ldmatrix.sync.aligned.m8n8.x4.shared.b16 {%0,%1,%2,%3},[%4];" \
        : "=r"((R)[0]), "=r"((R)[1]), "=r"((R)[2]), "=r"((R)[3]) : "r"(ADDR))

DINLINE u32 packh(float a, float b) {
    __half2 h = __floats2half2_rn(a, b);
    return *(u32*)&h;
}

DINLINE int edge_at(const void* p, int is64, int idx) {
    return is64 ? (int)((const long long*)p)[idx] : ((const int*)p)[idx];
}

// ---------------- fused edge prep: dtype detect + degree + rsqrt ----------------
__global__ void k_edge_prep(const void* __restrict__ ei) {
    __shared__ float sdeg[N_];
    __shared__ int nz;
    const int tid = threadIdx.x;   // 512 threads
    if (tid == 0) nz = 0;
    sdeg[tid] = 1.0f;              // self-loop
    __syncthreads();
    const int* ei32 = (const int*)ei;
    int acc = 0;
    for (int i = 1 + 2 * tid; i < 2 * E_; i += 1024) acc |= ei32[i];
    if (acc) atomicOr(&nz, 1);
    __syncthreads();
    int is64 = (nz == 0) ? 1 : 0;
    if (tid == 0) g_is64 = is64;
    for (int e = tid; e < E_; e += 512)
        atomicAdd(&sdeg[edge_at(ei, is64, E_ + e)], 1.0f);
    __syncthreads();
    g_dis[tid] = rsqrtf(sdeg[tid]);
}

// ---------------- weight prep: permute rows (4j+g), fp16-pair pack --------------
__global__ void k_prep_w(const float* __restrict__ w, u32* __restrict__ outw) {
    int i = blockIdx.x * blockDim.x + threadIdx.x;   // 512*64
    int colp = i >> 6, kp = i & 63;
    int j = colp >> 2, g = colp & 3;
    const float* wr = w + (g * H_ + j) * H_ + 2 * kp;
    outw[i] = packh(wr[0], wr[1]);
}

// two weight matrices in one launch (grid = 2*WN/256)
__global__ void k_prep_w2(const float* __restrict__ wa, const float* __restrict__ wb,
                          u32* __restrict__ outa, u32* __restrict__ outb2) {
    int gi = blockIdx.x * blockDim.x + threadIdx.x;   // 2*512*64
    int sel = gi >= (G4H * 64);
    int i = sel ? gi - G4H * 64 : gi;
    const float* w = sel ? wb : wa;
    u32* o = sel ? outb2 : outa;
    int colp = i >> 6, kp = i & 63;
    int j = colp >> 2, g = colp & 3;
    const float* wr = w + (g * H_ + j) * H_ + 2 * kp;
    o[i] = packh(wr[0], wr[1]);
}

__global__ void k_prep_b(const float* __restrict__ bi, const float* __restrict__ bh,
                         float* __restrict__ outb) {
    int colp = blockIdx.x * blockDim.x + threadIdx.x;
    if (colp < G4H) {
        int j = colp >> 2, g = colp & 3;
        outb[colp] = bi[g * H_ + j] + bh[g * H_ + j];
    }
}

__global__ void k_prep_bw0(const float* __restrict__ bi, const float* __restrict__ bh,
                           const float* __restrict__ w) {
    int colp = blockIdx.x * blockDim.x + threadIdx.x;
    if (colp < G4H) {
        int j = colp >> 2, g = colp & 3;
        g_br[0][colp] = bi[g * H_ + j] + bh[g * H_ + j];
        g_w0r[colp]   = w[g * H_ + j];
    }
}

// ---------------- gate fold: shuffle, input add, fp32 activations ----------------
template <int MODE>
DINLINE float gate_fold(const float* D, float& c_ref, const char* sm, bool evn,
                        int myrow, int t, uint2 xq, uint2 wh, uint2 bh) {
    float sv0 = evn ? D[2] : D[0];
    float rr0 = __shfl_xor_sync(0xffffffffu, sv0, 1);
    float sv1 = evn ? D[3] : D[1];
    float rr1 = __shfl_xor_sync(0xffffffffu, sv1, 1);
    float pi = evn ? D[0] : rr0;
    float pf = evn ? D[1] : rr1;
    float pg = evn ? rr0 : D[2];
    float po = evn ? rr1 : D[3];

    if (MODE == 1) {
        float2 fa = __half22float2(*(__half2*)&xq.x);
        float2 fb = __half22float2(*(__half2*)&xq.y);
        pi += fa.x; pf += fa.y; pg += fb.x; po += fb.y;
    } else {
        float xv = ((const float*)(sm + OFF_SX))[t * 32 + myrow];
        float2 wa = __half22float2(*(__half2*)&wh.x);
        float2 wb = __half22float2(*(__half2*)&wh.y);
        float2 ba = __half22float2(*(__half2*)&bh.x);
        float2 bb = __half22float2(*(__half2*)&bh.y);
        pi += xv * wa.x + ba.x;
        pf += xv * wa.y + ba.y;
        pg += xv * wb.x + bb.x;
        po += xv * wb.y + bb.y;
    }

    float si = fmaf(tanhfast(0.5f * pi), 0.5f, 0.5f);
    float sf = fmaf(tanhfast(0.5f * pf), 0.5f, 0.5f);
    float so = fmaf(tanhfast(0.5f * po), 0.5f, 0.5f);
    float cn = sf * c_ref + si * tanhfast(pg);
    c_ref = cn;
    return so * tanhfast(cn);
}

// ---------------- tensor-core LSTM recurrence ------------------------------------
// 512 threads, 16 warps. Warp w owns gate-cols [32w, 32w+32) for BOTH m-tiles;
// B fragments resident in 64 regs. xp for BOTH m-tiles prefetched at step top.
template <int MODE, int WRITE_ALL>
__global__ void __launch_bounds__(512, 1) rec_mma(
    const float* __restrict__ x,               // MODE 0
    const u32* __restrict__ w_h,               // [512][64] fp16 pairs
    const float* __restrict__ w0r,             // MODE 0
    const float* __restrict__ br0)             // MODE 0
{
    extern __shared__ __align__(16) char sm[];
    const u32 sbase = smem_u32(sm);

    const int tid = threadIdx.x, wid = tid >> 5, lane = tid & 31;
    const int grp = lane >> 2, tid4 = lane & 3;
    const bool evn = (tid4 & 1) == 0;
    const int cw = wid;                        // 32-col group
    const int s0 = blockIdx.x * 32;

    for (int i = tid; i < 512 * 64; i += 512) {
        int r = i >> 6, c = i & 63;
        *(u32*)(sm + OFF_W + r * WROW + c * 4) = w_h[i];
    }
    for (int i = tid; i < HPLANE / 4; i += 512)       // zero plane 0
        ((u32*)(sm + OFF_H))[i] = 0;
    if (MODE == 0) {
        float* sx = (float*)(sm + OFF_SX);
        for (int i = tid; i < 64 * 32; i += 512) {
            int t = i >> 5, m = i & 31;
            int s = s0 + m;
            sx[i] = x[(s >> 9) * (T_ * N_) + t * N_ + (s & (N_ - 1))];
        }
    }
    __syncthreads();

    const int qa = lane >> 3;
    const int a_loff = ((lane & 7) + (qa & 1) * 8) * WROW + ((qa >> 1) * 8) * 2;
    const int b_loff = (lane & 7) * WROW + qa * 16;
    const int rowoff = evn ? grp : grp + 8;

    // resident B fragments: 4 n-tiles x 8 ks x 2 regs = 64 regs
    u32 breg[4][8][2];
#pragma unroll
    for (int nt = 0; nt < 4; nt++) {
        const int n0 = cw * 32 + nt * 8;
#pragma unroll
        for (int kc = 0; kc < 4; kc++) {
            u32 r[4];
            LDSM4(r, sbase + OFF_W + n0 * WROW + b_loff + kc * 64);
            breg[nt][kc * 2][0] = r[0]; breg[nt][kc * 2][1] = r[1];
            breg[nt][kc * 2 + 1][0] = r[2]; breg[nt][kc * 2 + 1][1] = r[3];
        }
    }

    // MODE 0: loop-invariant w0/bias as fp16 registers (j = cw*8+nt*2+(tid4>>1))
    uint2 whr[4], bhr[4];
    if (MODE == 0) {
#pragma unroll
        for (int nt = 0; nt < 4; nt++) {
            int j = cw * 8 + nt * 2 + (tid4 >> 1);
            float4 w4 = ((const float4*)w0r)[j];
            float4 b4 = ((const float4*)br0)[j];
            whr[nt] = make_uint2(packh(w4.x, w4.y), packh(w4.z, w4.w));
            bhr[nt] = make_uint2(packh(b4.x, b4.y), packh(b4.z, b4.w));
        }
    }

    float c_st[8];
#pragma unroll
    for (int q = 0; q < 8; q++) c_st[q] = 0.0f;

    for (int t = 0; t < T_; t++) {
        const int rb = t & 1, wb = rb ^ 1;
        const int hw_off = OFF_H + wb * HPLANE;

        // prefetch xp for BOTH m-tiles before any shared work (hide DRAM latency)
        uint2 xq[2][4];
        if (MODE == 1) {
#pragma unroll
            for (int mt = 0; mt < 2; mt++) {
                const int myrow = mt * 16 + rowoff;
                const __half* xpb = g_xph + ((size_t)t * S_ + s0 + myrow) * G4H
                                    + cw * 32 + (tid4 >> 1) * 4;
#pragma unroll
                for (int nt = 0; nt < 4; nt++)
                    xq[mt][nt] = *(const uint2*)(xpb + nt * 8);
            }
        }

#pragma unroll
        for (int mt = 0; mt < 2; mt++) {
            const int myrow = mt * 16 + rowoff;

            float D[4][4];
#pragma unroll
            for (int nt = 0; nt < 4; nt++)
#pragma unroll
                for (int q = 0; q < 4; q++) D[nt][q] = 0.0f;

            const u32 a_base = sbase + OFF_H + rb * HPLANE + mt * 16 * WROW + a_loff;
#pragma unroll
            for (int kchunk = 0; kchunk < 2; kchunk++) {
                u32 ahi[4][4];
#pragma unroll
                for (int k4 = 0; k4 < 4; k4++)
                    LDSM4(ahi[k4], a_base + (kchunk * 4 + k4) * 32);
#pragma unroll
                for (int nt = 0; nt < 4; nt++)
#pragma unroll
                    for (int k4 = 0; k4 < 4; k4++)
                        mma_f16(D[nt], ahi[k4],
                                breg[nt][kchunk * 4 + k4][0],
                                breg[nt][kchunk * 4 + k4][1]);
            }

#pragma unroll
            for (int nt = 0; nt < 4; nt++) {
                float hv = gate_fold<MODE>(D[nt], c_st[mt * 4 + nt], sm, evn, myrow,
                                           t, xq[mt][nt], whr[nt], bhr[nt]);
                int j = cw * 8 + nt * 2 + (tid4 >> 1);
                *(__half*)(sm + hw_off + myrow * WROW + j * 2) = __float2half_rn(hv);
            }
        }

        __syncthreads();   // h(wb) complete; A-reads of rb done

        if (WRITE_ALL || t == T_ - 1) {
            for (int i = tid; i < 32 * 32; i += 512) {
                int r = i >> 5, jp4 = i & 31;
                uint2 v = *(const uint2*)(sm + hw_off + r * WROW + jp4 * 8);
                *(uint2*)&g_hh[((size_t)t * S_ + s0 + r) * H_ + jp4 * 4] = v;
            }
        }
    }
}

// ---------------- tensor-core input projection (persistent, 512 thr) -------------
__global__ void __launch_bounds__(512, 1) proj_mma(
    const u32* __restrict__ w_h,
    const float* __restrict__ br)
{
    extern __shared__ __align__(16) char sm[];
    const u32 sbase = smem_u32(sm);

    const int tid = threadIdx.x, wid = tid >> 5, lane = tid & 31;
    const int grp = lane >> 2, tid4 = lane & 3;
    const int cw = wid;

    for (int i = tid; i < 512 * 64; i += 512) {
        int r = i >> 6, c = i & 63;
        *(u32*)(sm + OFF_W + r * WROW + c * 4) = w_h[i];
    }
    __syncthreads();

    const int qa = lane >> 3;
    const int a_loff = ((lane & 7) + (qa & 1) * 8) * WROW + ((qa >> 1) * 8) * 2;
    const int b_loff = (lane & 7) * WROW + qa * 16;

    u32 breg[4][8][2];
    float2 bbv[4];
#pragma unroll
    for (int nt = 0; nt < 4; nt++) {
        const int n0 = cw * 32 + nt * 8;
#pragma unroll
        for (int kc = 0; kc < 4; kc++) {
            u32 r[4];
            LDSM4(r, sbase + OFF_W + n0 * WROW + b_loff + kc * 64);
            breg[nt][kc * 2][0] = r[0]; breg[nt][kc * 2][1] = r[1];
            breg[nt][kc * 2 + 1][0] = r[2]; breg[nt][kc * 2 + 1][1] = r[3];
        }
        bbv[nt] = *(const float2*)&br[n0 + tid4 * 2];
    }

    const int ntiles = (T_ * S_) / 128;   // 2048
    for (int rt = blockIdx.x; rt < ntiles; rt += gridDim.x) {
        __syncthreads();
        const u32* src = (const u32*)(g_hh + (size_t)rt * 128 * H_);
        for (int i = tid; i < 128 * 64; i += 512) {
            int row = i >> 6, kp = i & 63;
            *(u32*)(sm + OFF_AH + row * WROW + kp * 4) = src[i];
        }
        __syncthreads();

#pragma unroll 1
        for (int mt = 0; mt < 8; mt++) {
            u32 ahi[8][4];
            const u32 abase = sbase + OFF_AH + mt * 16 * WROW + a_loff;
#pragma unroll
            for (int ks = 0; ks < 8; ks++) LDSM4(ahi[ks], abase + ks * 32);

#pragma unroll
            for (int nt = 0; nt < 4; nt++) {
                const int n0 = cw * 32 + nt * 8;
                float D[4] = {bbv[nt].x, bbv[nt].y, bbv[nt].x, bbv[nt].y};
#pragma unroll
                for (int ks = 0; ks < 8; ks++)
                    mma_f16(D, ahi[ks], breg[nt][ks][0], breg[nt][ks][1]);

                size_t rowA = ((size_t)rt * 128 + mt * 16 + grp) * G4H;
                size_t rowB = rowA + 8 * G4H;
                *(u32*)&g_xph[rowA + n0 + tid4 * 2] = packh(D[0], D[1]);
                *(u32*)&g_xph[rowB + n0 + tid4 * 2] = packh(D[2], D[3]);
            }
        }
    }
}

// ---------------- GCN -------------------------------------------------------------
__global__ void k_lin1(const float* __restrict__ w, const float* __restrict__ bias) {
    __shared__ float fr[8][H_];
    int r0 = blockIdx.x * 8, tid = threadIdx.x;   // 512 blocks, 128 thr
    for (int i = tid; i < 8 * H_; i += 128) {
        int r = i >> 7, k = i & 127;
        fr[r][k] = __half2float(g_hh[((size_t)(T_ - 1) * S_ + r0 + r) * H_ + k]);
    }
    __syncthreads();
    const float* wr = w + tid * H_;
    float acc[8] = {0, 0, 0, 0, 0, 0, 0, 0};
#pragma unroll 4
    for (int k = 0; k < H_; k++) {
        float wk = wr[k];
#pragma unroll
        for (int r = 0; r < 8; r++) acc[r] = fmaf(fr[r][k], wk, acc[r]);
    }
    float bv = bias[tid];
#pragma unroll
    for (int r = 0; r < 8; r++) {
        g_xl1[(r0 + r) * G1_ + tid] = acc[r];
        float d = g_dis[(r0 + r) & (N_ - 1)];
        g_h1[(r0 + r) * G1_ + tid] = bv + acc[r] * d * d;
    }
}

__global__ void k_lin2(const float* __restrict__ w, const float* __restrict__ bias) {
    __shared__ float fr[8][G1_];
    int r0 = blockIdx.x * 8, tid = threadIdx.x;   // 512 blocks, 64 thr
    for (int i = tid; i < 8 * G1_; i += 64) {
        int r = i >> 7, k = i & 127;
        fr[r][k] = fmaxf(g_h1[(r0 + r) * G1_ + k], 0.0f);
    }
    __syncthreads();
    const float* wr = w + tid * G1_;
    float acc[8] = {0, 0, 0, 0, 0, 0, 0, 0};
#pragma unroll 4
    for (int k = 0; k < G1_; k++) {
        float wk = wr[k];
#pragma unroll
        for (int r = 0; r < 8; r++) acc[r] = fmaf(fr[r][k], wk, acc[r]);
    }
    float bv = bias[tid];
#pragma unroll
    for (int r = 0; r < 8; r++) {
        g_xl2[(r0 + r) * G2_ + tid] = acc[r];
        float d = g_dis[(r0 + r) & (N_ - 1)];
        g_h2[(r0 + r) * G2_ + tid] = bv + acc[r] * d * d;
    }
}

// one thread per (edge, g4); loops over all batches (reuses indices + norm)
template <int Gd>
__global__ void k_agg_edge(const void* __restrict__ ei) {
    constexpr int G4 = Gd / 4;
    const float* xl = (Gd == G1_) ? g_xl1 : g_xl2;
    float* outb     = (Gd == G1_) ? g_h1  : g_h2;
    int i = blockIdx.x * blockDim.x + threadIdx.x;
    if (i >= E_ * G4) return;
    int e = i / G4;
    int g4 = i - e * G4;
    int is64 = g_is64;
    int src = edge_at(ei, is64, e);
    int dst = edge_at(ei, is64, E_ + e);
    float norm = g_dis[src] * g_dis[dst];
    const float* sp = xl + src * Gd + g4 * 4;
    float* dp = outb + dst * Gd + g4 * 4;
#pragma unroll
    for (int b = 0; b < B_; b++) {
        float4 v = *(const float4*)(sp + (size_t)b * (N_ * Gd));
        float* o = dp + (size_t)b * (N_ * Gd);
        atomicAdd(o + 0, v.x * norm);
        atomicAdd(o + 1, v.y * norm);
        atomicAdd(o + 2, v.z * norm);
        atomicAdd(o + 3, v.w * norm);
    }
}

__global__ void k_final(const float* __restrict__ cls_w,
                        const float* __restrict__ cls_b,
                        float* __restrict__ out) {
    int b = blockIdx.x, tid = threadIdx.x;
    __shared__ float red[256];
    float a = 0.0f;
    for (int i = tid; i < N_ * G2_; i += 256) {
        int g = i & (G2_ - 1);
        a = fmaf(fmaxf(g_h2[b * (N_ * G2_) + i], 0.0f), cls_w[g], a);
    }
    red[tid] = a;
    __syncthreads();
    for (int s = 128; s > 0; s >>= 1) {
        if (tid < s) red[tid] += red[tid + s];
        __syncthreads();
    }
    if (tid == 0) out[b] = red[0] * (1.0f / N_) + cls_b[0];
}

// ---------------- launch -----------------------------------------------------------
extern "C" void kernel_launch(void* const* d_in, const int* in_sizes, int n_in,
                              void* d_out, int out_size) {
    const float* x      = (const float*)d_in[0];
    const void*  ei     = d_in[1];
    const float* w_ih0  = (const float*)d_in[2];
    const float* w_hh0  = (const float*)d_in[3];
    const float* b_ih0  = (const float*)d_in[4];
    const float* b_hh0  = (const float*)d_in[5];
    const float* w_ih1  = (const float*)d_in[6];
    const float* w_hh1  = (const float*)d_in[7];
    const float* b_ih1  = (const float*)d_in[8];
    const float* b_hh1  = (const float*)d_in[9];
    const float* w_ih2  = (const float*)d_in[10];
    const float* w_hh2  = (const float*)d_in[11];
    const float* b_ih2  = (const float*)d_in[12];
    const float* b_hh2  = (const float*)d_in[13];
    const float* gcn1_w = (const float*)d_in[14];
    const float* gcn1_b = (const float*)d_in[15];
    const float* gcn2_w = (const float*)d_in[16];
    const float* gcn2_b = (const float*)d_in[17];
    const float* cls_w  = (const float*)d_in[18];
    const float* cls_b  = (const float*)d_in[19];
    float* out = (float*)d_out;

    u32 *whh, *wih;
    float *br, *w0r;
    cudaGetSymbolAddress((void**)&whh, g_whh_h);
    cudaGetSymbolAddress((void**)&wih, g_wih_h);
    cudaGetSymbolAddress((void**)&br, g_br);
    cudaGetSymbolAddress((void**)&w0r, g_w0r);

    cudaFuncSetAttribute(rec_mma<0, 1>, cudaFuncAttributeMaxDynamicSharedMemorySize, REC_SM);
    cudaFuncSetAttribute(rec_mma<1, 1>, cudaFuncAttributeMaxDynamicSharedMemorySize, REC_SM);
    cudaFuncSetAttribute(rec_mma<1, 0>, cudaFuncAttributeMaxDynamicSharedMemorySize, REC_SM);
    cudaFuncSetAttribute(proj_mma, cudaFuncAttributeMaxDynamicSharedMemorySize, PROJ_SM);

    constexpr int WN = G4H * 64;
    const int RB = S_ / 32;   // 128 blocks

    // launches 1-5 (setup + rec0), 6 = proj_mma so ncu (-s 5 -c 1) profiles it
    k_edge_prep<<<1, 512>>>(ei);                                   // 1
    k_prep_w2<<<2 * WN / 256, 256>>>(w_hh0, w_ih1,
                                     whh + 0 * WN, wih + 0 * WN);  // 2
    k_prep_bw0<<<2, 256>>>(b_ih0, b_hh0, w_ih0);                   // 3
    k_prep_b<<<2, 256>>>(b_ih1, b_hh1, br + 1 * G4H);              // 4
    rec_mma<0, 1><<<RB, 512, REC_SM>>>(x, whh + 0 * WN, w0r, br + 0 * G4H);  // 5
    proj_mma<<<148, 512, PROJ_SM>>>(wih + 0 * WN, br + 1 * G4H);   // 6 <- profiled

    k_prep_w2<<<2 * WN / 256, 256>>>(w_hh1, w_ih2,
                                     whh + 1 * WN, wih + 1 * WN);
    k_prep_b<<<2, 256>>>(b_ih2, b_hh2, br + 2 * G4H);
    rec_mma<1, 1><<<RB, 512, REC_SM>>>(nullptr, whh + 1 * WN, nullptr, nullptr);

    proj_mma<<<148, 512, PROJ_SM>>>(wih + 1 * WN, br + 2 * G4H);
    k_prep_w<<<WN / 256, 256>>>(w_hh2, whh + 2 * WN);
    rec_mma<1, 0><<<RB, 512, REC_SM>>>(nullptr, whh + 2 * WN, nullptr, nullptr);

    // GCN
    k_lin1<<<S_ / 8, 128>>>(gcn1_w, gcn1_b);
    k_agg_edge<G1_><<<(E_ * (G1_ / 4) + 255) / 256, 256>>>(ei);
    k_lin2<<<S_ / 8, 64>>>(gcn2_w, gcn2_b);
    k_agg_edge<G2_><<<(E_ * (G2_ / 4) + 255) / 256, 256>>>(ei);
    k_final<<<B_, 256>>>(cls_w, cls_b, out);
}

// round 15
// speedup vs baseline: 1.0363x; 1.0363x over previous
#include <cuda_runtime.h>
#include <cuda_fp16.h>

#define DINLINE __device__ __forceinline__
typedef unsigned int u32;
typedef unsigned short u16;

constexpr int B_ = 8, T_ = 64, N_ = 512, H_ = 128, E_ = 8192;
constexpr int S_ = B_ * N_;       // 4096 sequences
constexpr int G1_ = 128, G2_ = 64;
constexpr int G4H = 4 * H_;       // 512 gate rows

// ---------------- SMEM layout (byte offsets) -----------------------------------
constexpr int WROW    = 272;                   // 136 fp16 per row (128 + 8 pad)
constexpr int OFF_W   = 0;                     // 512*272 = 139264
constexpr int OFF_H   = 139264;                // h planes (2 x 32 x 272), fp16
constexpr int HPLANE  = 32 * WROW;             // 8704
constexpr int OFF_SX  = OFF_H + 2 * HPLANE;    // 156672 (MODE 0 only): 8192 B
constexpr int OFF_W0S = OFF_SX + 8192;
constexpr int OFF_BRS = OFF_W0S + 2048;
constexpr int REC_SM  = OFF_BRS + 2048;        // 168960

constexpr int OFF_AH  = 139264;                // proj: A plane 128*272
constexpr int APLANE  = 128 * WROW;            // 34816
constexpr int PROJ_SM = OFF_AH + APLANE;       // 174080

// ---------------- device scratch (static globals; no allocation) ---------------
__device__ __half g_hh [(size_t)T_ * S_ * H_];   // [t*S+s][j]    64 MiB
__device__ __half g_xph[(size_t)T_ * S_ * G4H];  // [t*S+s][4j+g] 256 MiB
__device__ u32   g_whh_h[3][G4H * 64];           // permuted fp16-pair W_hh
__device__ u32   g_wih_h[2][G4H * 64];           // permuted fp16-pair W_ih
__device__ float g_br[3][G4H];                   // b_ih+b_hh permuted (4j+g)
__device__ float g_w0r[G4H];                     // w_ih0 permuted
__device__ float g_xl1[S_ * G1_];
__device__ float g_h1[S_ * G1_];
__device__ float g_xl2[S_ * G2_];
__device__ float g_h2[S_ * G2_];
__device__ float g_dis[N_];
__device__ int   g_is64;

// ---------------- helpers -------------------------------------------------------
DINLINE float tanhfast(float x) {
    float y;
    asm("tanh.approx.f32 %0, %1;" : "=f"(y) : "f"(x));
    return y;
}

DINLINE u32 smem_u32(const void* p) {
    u32 a;
    asm("{ .reg .u64 t; cvta.to.shared.u64 t, %1; cvt.u32.u64 %0, t; }" : "=r"(a) : "l"(p));
    return a;
}

DINLINE void mma_f16(float* D, const u32* A, u32 b0, u32 b1) {
    asm("mma.sync.aligned.m16n8k16.row.col.f32.f16.f16.f32 "
        "{%0,%1,%2,%3},{%4,%5,%6,%7},{%8,%9},{%0,%1,%2,%3};"
        : "+f"(D[0]), "+f"(D[1]), "+f"(D[2]), "+f"(D[3])
        : "r"(A[0]), "r"(A[1]), "r"(A[2]), "r"(A[3]), "r"(b0), "r"(b1));
}

#define LDSM4(R, ADDR) \
    asm volatile("ldmatrix.sync.aligned.m8n8.x4.shared.b16 {%0,%1,%2,%3},[%4];" \
        : "=r"((R)[0]), "=r"((R)[1]), "=r"((R)[2]), "=r"((R)[3]) : "r"(ADDR))

DINLINE u32 packh(float a, float b) {
    __half2 h = __floats2half2_rn(a, b);
    return *(u32*)&h;
}

DINLINE int edge_at(const void* p, int is64, int idx) {
    return is64 ? (int)((const long long*)p)[idx] : ((const int*)p)[idx];
}

// ---------------- fused edge prep: dtype detect + degree + rsqrt ----------------
__global__ void k_edge_prep(const void* __restrict__ ei) {
    __shared__ float sdeg[N_];
    __shared__ int nz;
    const int tid = threadIdx.x;   // 512 threads
    if (tid == 0) nz = 0;
    sdeg[tid] = 1.0f;              // self-loop
    __syncthreads();
    const int* ei32 = (const int*)ei;
    int acc = 0;
    for (int i = 1 + 2 * tid; i < 2 * E_; i += 1024) acc |= ei32[i];
    if (acc) atomicOr(&nz, 1);
    __syncthreads();
    int is64 = (nz == 0) ? 1 : 0;
    if (tid == 0) g_is64 = is64;
    for (int e = tid; e < E_; e += 512)
        atomicAdd(&sdeg[edge_at(ei, is64, E_ + e)], 1.0f);
    __syncthreads();
    g_dis[tid] = rsqrtf(sdeg[tid]);
}

// ---------------- weight prep: 5 matrices in one launch --------------------------
// order: whh0, whh1, whh2, wih1, wih2
__global__ void k_prep_w5(const float* __restrict__ w0, const float* __restrict__ w1,
                          const float* __restrict__ w2, const float* __restrict__ w3,
                          const float* __restrict__ w4) {
    constexpr int WN = G4H * 64;
    int gi = blockIdx.x * blockDim.x + threadIdx.x;   // 5*WN
    int sel = gi / WN;
    int i = gi - sel * WN;
    const float* w = (sel == 0) ? w0 : (sel == 1) ? w1 : (sel == 2) ? w2
                   : (sel == 3) ? w3 : w4;
    u32* o = (sel < 3) ? &g_whh_h[sel][0] : &g_wih_h[sel - 3][0];
    int colp = i >> 6, kp = i & 63;
    int j = colp >> 2, g = colp & 3;
    const float* wr = w + (g * H_ + j) * H_ + 2 * kp;
    o[i] = packh(wr[0], wr[1]);
}

// biases for layers 1 and 2 in one launch; plus layer-0 bias + w0
__global__ void k_prep_b2(const float* __restrict__ bi1, const float* __restrict__ bh1,
                          const float* __restrict__ bi2, const float* __restrict__ bh2) {
    int gi = blockIdx.x * blockDim.x + threadIdx.x;   // 2*G4H
    int l = gi >= G4H;
    int colp = gi - l * G4H;
    const float* bi = l ? bi2 : bi1;
    const float* bh = l ? bh2 : bh1;
    int j = colp >> 2, g = colp & 3;
    g_br[1 + l][colp] = bi[g * H_ + j] + bh[g * H_ + j];
}

__global__ void k_prep_bw0(const float* __restrict__ bi, const float* __restrict__ bh,
                           const float* __restrict__ w) {
    int colp = blockIdx.x * blockDim.x + threadIdx.x;
    if (colp < G4H) {
        int j = colp >> 2, g = colp & 3;
        g_br[0][colp] = bi[g * H_ + j] + bh[g * H_ + j];
        g_w0r[colp]   = w[g * H_ + j];
    }
}

// ---------------- gate fold: shuffle, input add, activations, h write ------------
template <int MODE>
DINLINE void gate_fold(float* D, float& c_ref, char* sm, bool evn,
                       int myrow, int j, int t, int hw_off, uint2 xq) {
    float sv0 = evn ? D[2] : D[0];
    float rr0 = __shfl_xor_sync(0xffffffffu, sv0, 1);
    float sv1 = evn ? D[3] : D[1];
    float rr1 = __shfl_xor_sync(0xffffffffu, sv1, 1);
    float pi = evn ? D[0] : rr0;
    float pf = evn ? D[1] : rr1;
    float pg = evn ? rr0 : D[2];
    float po = evn ? rr1 : D[3];

    if (MODE == 1) {
        float2 fa = __half22float2(*(__half2*)&xq.x);
        float2 fb = __half22float2(*(__half2*)&xq.y);
        pi += fa.x; pf += fa.y; pg += fb.x; po += fb.y;
    } else {
        float xv = ((const float*)(sm + OFF_SX))[t * 32 + myrow];
        float4 w4 = ((const float4*)(sm + OFF_W0S))[j];
        float4 b4 = ((const float4*)(sm + OFF_BRS))[j];
        pi += xv * w4.x + b4.x;
        pf += xv * w4.y + b4.y;
        pg += xv * w4.z + b4.z;
        po += xv * w4.w + b4.w;
    }

    float si = fmaf(tanhfast(0.5f * pi), 0.5f, 0.5f);
    float sf = fmaf(tanhfast(0.5f * pf), 0.5f, 0.5f);
    float so = fmaf(tanhfast(0.5f * po), 0.5f, 0.5f);
    float cn = sf * c_ref + si * tanhfast(pg);
    c_ref = cn;
    float hv = so * tanhfast(cn);

    *(__half*)(sm + hw_off + myrow * WROW + j * 2) = __float2half_rn(hv);
}

// ---------------- tensor-core LSTM recurrence ------------------------------------
// 512 threads, 16 warps. Warp w owns gate-cols [32w, 32w+32) for BOTH m-tiles;
// B fragments resident in 64 regs, loaded once. Per-mt xp prefetch (transient).
template <int MODE, int WRITE_ALL>
__global__ void __launch_bounds__(512, 1) rec_mma(
    const float* __restrict__ x,               // MODE 0
    const u32* __restrict__ w_h,               // [512][64] fp16 pairs
    const float* __restrict__ w0r,             // MODE 0
    const float* __restrict__ br0)             // MODE 0
{
    extern __shared__ __align__(16) char sm[];
    const u32 sbase = smem_u32(sm);

    const int tid = threadIdx.x, wid = tid >> 5, lane = tid & 31;
    const int grp = lane >> 2, tid4 = lane & 3;
    const bool evn = (tid4 & 1) == 0;
    const int cw = wid;                        // 32-col group
    const int s0 = blockIdx.x * 32;

    for (int i = tid; i < 512 * 64; i += 512) {
        int r = i >> 6, c = i & 63;
        *(u32*)(sm + OFF_W + r * WROW + c * 4) = w_h[i];
    }
    for (int i = tid; i < HPLANE / 4; i += 512)       // zero plane 0
        ((u32*)(sm + OFF_H))[i] = 0;
    if (MODE == 0) {
        float* sx = (float*)(sm + OFF_SX);
        for (int i = tid; i < 64 * 32; i += 512) {
            int t = i >> 5, m = i & 31;
            int s = s0 + m;
            sx[i] = x[(s >> 9) * (T_ * N_) + t * N_ + (s & (N_ - 1))];
        }
        if (tid < 512) {
            ((float*)(sm + OFF_W0S))[tid] = w0r[tid];
            ((float*)(sm + OFF_BRS))[tid] = br0[tid];
        }
    }
    __syncthreads();

    const int qa = lane >> 3;
    const int a_loff = ((lane & 7) + (qa & 1) * 8) * WROW + ((qa >> 1) * 8) * 2;
    const int b_loff = (lane & 7) * WROW + qa * 16;
    const int rowoff = evn ? grp : grp + 8;

    // resident B fragments: 4 n-tiles x 8 ks x 2 regs = 64 regs
    u32 breg[4][8][2];
#pragma unroll
    for (int nt = 0; nt < 4; nt++) {
        const int n0 = cw * 32 + nt * 8;
#pragma unroll
        for (int kc = 0; kc < 4; kc++) {
            u32 r[4];
            LDSM4(r, sbase + OFF_W + n0 * WROW + b_loff + kc * 64);
            breg[nt][kc * 2][0] = r[0]; breg[nt][kc * 2][1] = r[1];
            breg[nt][kc * 2 + 1][0] = r[2]; breg[nt][kc * 2 + 1][1] = r[3];
        }
    }

    float c_st[8];
#pragma unroll
    for (int q = 0; q < 8; q++) c_st[q] = 0.0f;

    for (int t = 0; t < T_; t++) {
        const int rb = t & 1, wb = rb ^ 1;
        const int hw_off = OFF_H + wb * HPLANE;

#pragma unroll
        for (int mt = 0; mt < 2; mt++) {
            const int myrow = mt * 16 + rowoff;

            // prefetch xp for this m-tile (transient; self-consumed)
            uint2 xq[4];
            if (MODE == 1) {
                const __half* xpb = g_xph + ((size_t)t * S_ + s0 + myrow) * G4H
                                    + cw * 32 + (tid4 >> 1) * 4;
#pragma unroll
                for (int nt = 0; nt < 4; nt++)
                    xq[nt] = *(const uint2*)(xpb + nt * 8);
            }

            float D[4][4];
#pragma unroll
            for (int nt = 0; nt < 4; nt++)
#pragma unroll
                for (int q = 0; q < 4; q++) D[nt][q] = 0.0f;

            const u32 a_base = sbase + OFF_H + rb * HPLANE + mt * 16 * WROW + a_loff;
#pragma unroll
            for (int kchunk = 0; kchunk < 2; kchunk++) {
                u32 ahi[4][4];
#pragma unroll
                for (int k4 = 0; k4 < 4; k4++)
                    LDSM4(ahi[k4], a_base + (kchunk * 4 + k4) * 32);
#pragma unroll
                for (int nt = 0; nt < 4; nt++)
#pragma unroll
                    for (int k4 = 0; k4 < 4; k4++)
                        mma_f16(D[nt], ahi[k4],
                                breg[nt][kchunk * 4 + k4][0],
                                breg[nt][kchunk * 4 + k4][1]);
            }

#pragma unroll
            for (int nt = 0; nt < 4; nt++)
                gate_fold<MODE>(D[nt], c_st[mt * 4 + nt], sm, evn, myrow,
                                cw * 8 + nt * 2 + (tid4 >> 1), t, hw_off, xq[nt]);
        }

        __syncthreads();   // h(wb) complete; A-reads of rb done

        if (WRITE_ALL || t == T_ - 1) {
            for (int i = tid; i < 32 * 32; i += 512) {
                int r = i >> 5, jp4 = i & 31;
                uint2 v = *(const uint2*)(sm + hw_off + r * WROW + jp4 * 8);
                *(uint2*)&g_hh[((size_t)t * S_ + s0 + r) * H_ + jp4 * 4] = v;
            }
        }
    }
}

// ---------------- tensor-core input projection (persistent, 512 thr) -------------
// Warp w owns cols [32w, 32w+32) with resident B fragments; loops over 8 m-tiles.
__global__ void __launch_bounds__(512, 1) proj_mma(
    const u32* __restrict__ w_h,
    const float* __restrict__ br)
{
    extern __shared__ __align__(16) char sm[];
    const u32 sbase = smem_u32(sm);

    const int tid = threadIdx.x, wid = tid >> 5, lane = tid & 31;
    const int grp = lane >> 2, tid4 = lane & 3;
    const int cw = wid;

    for (int i = tid; i < 512 * 64; i += 512) {
        int r = i >> 6, c = i & 63;
        *(u32*)(sm + OFF_W + r * WROW + c * 4) = w_h[i];
    }
    __syncthreads();

    const int qa = lane >> 3;
    const int a_loff = ((lane & 7) + (qa & 1) * 8) * WROW + ((qa >> 1) * 8) * 2;
    const int b_loff = (lane & 7) * WROW + qa * 16;

    // resident B fragments + bias
    u32 breg[4][8][2];
    float2 bbv[4];
#pragma unroll
    for (int nt = 0; nt < 4; nt++) {
        const int n0 = cw * 32 + nt * 8;
#pragma unroll
        for (int kc = 0; kc < 4; kc++) {
            u32 r[4];
            LDSM4(r, sbase + OFF_W + n0 * WROW + b_loff + kc * 64);
            breg[nt][kc * 2][0] = r[0]; breg[nt][kc * 2][1] = r[1];
            breg[nt][kc * 2 + 1][0] = r[2]; breg[nt][kc * 2 + 1][1] = r[3];
        }
        bbv[nt] = *(const float2*)&br[n0 + tid4 * 2];
    }

    const int ntiles = (T_ * S_) / 128;   // 2048
    for (int rt = blockIdx.x; rt < ntiles; rt += gridDim.x) {
        __syncthreads();
        const u32* src = (const u32*)(g_hh + (size_t)rt * 128 * H_);
        for (int i = tid; i < 128 * 64; i += 512) {
            int row = i >> 6, kp = i & 63;
            *(u32*)(sm + OFF_AH + row * WROW + kp * 4) = src[i];
        }
        __syncthreads();

#pragma unroll 1
        for (int mt = 0; mt < 8; mt++) {
            u32 ahi[8][4];
            const u32 abase = sbase + OFF_AH + mt * 16 * WROW + a_loff;
#pragma unroll
            for (int ks = 0; ks < 8; ks++) LDSM4(ahi[ks], abase + ks * 32);

#pragma unroll
            for (int nt = 0; nt < 4; nt++) {
                const int n0 = cw * 32 + nt * 8;
                float D[4] = {bbv[nt].x, bbv[nt].y, bbv[nt].x, bbv[nt].y};
#pragma unroll
                for (int ks = 0; ks < 8; ks++)
                    mma_f16(D, ahi[ks], breg[nt][ks][0], breg[nt][ks][1]);

                size_t rowA = ((size_t)rt * 128 + mt * 16 + grp) * G4H;
                size_t rowB = rowA + 8 * G4H;
                *(u32*)&g_xph[rowA + n0 + tid4 * 2] = packh(D[0], D[1]);
                *(u32*)&g_xph[rowB + n0 + tid4 * 2] = packh(D[2], D[3]);
            }
        }
    }
}

// ---------------- GCN -------------------------------------------------------------
__global__ void k_lin1(const float* __restrict__ w, const float* __restrict__ bias) {
    __shared__ float fr[8][H_];
    int r0 = blockIdx.x * 8, tid = threadIdx.x;   // 512 blocks, 128 thr
    for (int i = tid; i < 8 * H_; i += 128) {
        int r = i >> 7, k = i & 127;
        fr[r][k] = __half2float(g_hh[((size_t)(T_ - 1) * S_ + r0 + r) * H_ + k]);
    }
    __syncthreads();
    const float* wr = w + tid * H_;
    float acc[8] = {0, 0, 0, 0, 0, 0, 0, 0};
#pragma unroll 4
    for (int k = 0; k < H_; k++) {
        float wk = wr[k];
#pragma unroll
        for (int r = 0; r < 8; r++) acc[r] = fmaf(fr[r][k], wk, acc[r]);
    }
    float bv = bias[tid];
#pragma unroll
    for (int r = 0; r < 8; r++) {
        g_xl1[(r0 + r) * G1_ + tid] = acc[r];
        float d = g_dis[(r0 + r) & (N_ - 1)];
        g_h1[(r0 + r) * G1_ + tid] = bv + acc[r] * d * d;
    }
}

__global__ void k_lin2(const float* __restrict__ w, const float* __restrict__ bias) {
    __shared__ float fr[8][G1_];
    int r0 = blockIdx.x * 8, tid = threadIdx.x;   // 512 blocks, 64 thr
    for (int i = tid; i < 8 * G1_; i += 64) {
        int r = i >> 7, k = i & 127;
        fr[r][k] = fmaxf(g_h1[(r0 + r) * G1_ + k], 0.0f);
    }
    __syncthreads();
    const float* wr = w + tid * G1_;
    float acc[8] = {0, 0, 0, 0, 0, 0, 0, 0};
#pragma unroll 4
    for (int k = 0; k < G1_; k++) {
        float wk = wr[k];
#pragma unroll
        for (int r = 0; r < 8; r++) acc[r] = fmaf(fr[r][k], wk, acc[r]);
    }
    float bv = bias[tid];
#pragma unroll
    for (int r = 0; r < 8; r++) {
        g_xl2[(r0 + r) * G2_ + tid] = acc[r];
        float d = g_dis[(r0 + r) & (N_ - 1)];
        g_h2[(r0 + r) * G2_ + tid] = bv + acc[r] * d * d;
    }
}

template <int Gd>
__global__ void k_agg_edge(const void* __restrict__ ei) {
    constexpr int G4 = Gd / 4;
    const float* xl = (Gd == G1_) ? g_xl1 : g_xl2;
    float* outb     = (Gd == G1_) ? g_h1  : g_h2;
    int i = blockIdx.x * blockDim.x + threadIdx.x;
    constexpr int per = B_ * G4;
    if (i >= E_ * per) return;
    int e = i / per;
    int r = i - e * per;
    int b = r / G4;
    int g4 = r - b * G4;
    int is64 = g_is64;
    int src = edge_at(ei, is64, e);
    int dst = edge_at(ei, is64, E_ + e);
    float norm = g_dis[src] * g_dis[dst];
    float4 v = *(const float4*)&xl[(b * N_ + src) * Gd + g4 * 4];
    float* o = &outb[(b * N_ + dst) * Gd + g4 * 4];
    atomicAdd(o + 0, v.x * norm);
    atomicAdd(o + 1, v.y * norm);
    atomicAdd(o + 2, v.z * norm);
    atomicAdd(o + 3, v.w * norm);
}

__global__ void k_final(const float* __restrict__ cls_w,
                        const float* __restrict__ cls_b,
                        float* __restrict__ out) {
    int b = blockIdx.x, tid = threadIdx.x;
    __shared__ float red[256];
    float a = 0.0f;
    for (int i = tid; i < N_ * G2_; i += 256) {
        int g = i & (G2_ - 1);
        a = fmaf(fmaxf(g_h2[b * (N_ * G2_) + i], 0.0f), cls_w[g], a);
    }
    red[tid] = a;
    __syncthreads();
    for (int s = 128; s > 0; s >>= 1) {
        if (tid < s) red[tid] += red[tid + s];
        __syncthreads();
    }
    if (tid == 0) out[b] = red[0] * (1.0f / N_) + cls_b[0];
}

// ---------------- launch -----------------------------------------------------------
extern "C" void kernel_launch(void* const* d_in, const int* in_sizes, int n_in,
                              void* d_out, int out_size) {
    const float* x      = (const float*)d_in[0];
    const void*  ei     = d_in[1];
    const float* w_ih0  = (const float*)d_in[2];
    const float* w_hh0  = (const float*)d_in[3];
    const float* b_ih0  = (const float*)d_in[4];
    const float* b_hh0  = (const float*)d_in[5];
    const float* w_ih1  = (const float*)d_in[6];
    const float* w_hh1  = (const float*)d_in[7];
    const float* b_ih1  = (const float*)d_in[8];
    const float* b_hh1  = (const float*)d_in[9];
    const float* w_ih2  = (const float*)d_in[10];
    const float* w_hh2  = (const float*)d_in[11];
    const float* b_ih2  = (const float*)d_in[12];
    const float* b_hh2  = (const float*)d_in[13];
    const float* gcn1_w = (const float*)d_in[14];
    const float* gcn1_b = (const float*)d_in[15];
    const float* gcn2_w = (const float*)d_in[16];
    const float* gcn2_b = (const float*)d_in[17];
    const float* cls_w  = (const float*)d_in[18];
    const float* cls_b  = (const float*)d_in[19];
    float* out = (float*)d_out;

    u32 *whh, *wih;
    float *br, *w0r;
    cudaGetSymbolAddress((void**)&whh, g_whh_h);
    cudaGetSymbolAddress((void**)&wih, g_wih_h);
    cudaGetSymbolAddress((void**)&br, g_br);
    cudaGetSymbolAddress((void**)&w0r, g_w0r);

    cudaFuncSetAttribute(rec_mma<0, 1>, cudaFuncAttributeMaxDynamicSharedMemorySize, REC_SM);
    cudaFuncSetAttribute(rec_mma<1, 1>, cudaFuncAttributeMaxDynamicSharedMemorySize, REC_SM);
    cudaFuncSetAttribute(rec_mma<1, 0>, cudaFuncAttributeMaxDynamicSharedMemorySize, REC_SM);
    cudaFuncSetAttribute(proj_mma, cudaFuncAttributeMaxDynamicSharedMemorySize, PROJ_SM);

    constexpr int WN = G4H * 64;
    const int RB = S_ / 32;   // 128 blocks

    // prep (all independent, up front)
    k_edge_prep<<<1, 512>>>(ei);
    k_prep_w5<<<5 * WN / 256, 256>>>(w_hh0, w_hh1, w_hh2, w_ih1, w_ih2);
    k_prep_bw0<<<2, 256>>>(b_ih0, b_hh0, w_ih0);
    k_prep_b2<<<4, 256>>>(b_ih1, b_hh1, b_ih2, b_hh2);

    // layer 0
    rec_mma<0, 1><<<RB, 512, REC_SM>>>(x, whh + 0 * WN, w0r, br + 0 * G4H);
    // layer 1
    proj_mma<<<148, 512, PROJ_SM>>>(wih + 0 * WN, br + 1 * G4H);
    rec_mma<1, 1><<<RB, 512, REC_SM>>>(nullptr, whh + 1 * WN, nullptr, nullptr);
    // layer 2
    proj_mma<<<148, 512, PROJ_SM>>>(wih + 1 * WN, br + 2 * G4H);
    rec_mma<1, 0><<<RB, 512, REC_SM>>>(nullptr, whh + 2 * WN, nullptr, nullptr);

    // GCN
    k_lin1<<<S_ / 8, 128>>>(gcn1_w, gcn1_b);
    k_agg_edge<G1_><<<(E_ * B_ * (G1_ / 4) + 255) / 256, 256>>>(ei);
    k_lin2<<<S_ / 8, 64>>>(gcn2_w, gcn2_b);
    k_agg_edge<G2_><<<(E_ * B_ * (G2_ / 4) + 255) / 256, 256>>>(ei);
    k_final<<<B_, 256>>>(cls_w, cls_b, out);
}

// round 16
// speedup vs baseline: 1.0454x; 1.0087x over previous
#include <cuda_runtime.h>
#include <cuda_fp16.h>

#define DINLINE __device__ __forceinline__
typedef unsigned int u32;
typedef unsigned short u16;

constexpr int B_ = 8, T_ = 64, N_ = 512, H_ = 128, E_ = 8192;
constexpr int S_ = B_ * N_;       // 4096 sequences
constexpr int G1_ = 128, G2_ = 64;
constexpr int G4H = 4 * H_;       // 512 gate rows

// ---------------- SMEM layout (byte offsets) -----------------------------------
constexpr int WROW    = 272;                   // 136 fp16 per row (128 + 8 pad)
constexpr int OFF_W   = 0;                     // 512*272 = 139264
constexpr int OFF_H   = 139264;                // h planes (2 x 32 x 272), fp16
constexpr int HPLANE  = 32 * WROW;             // 8704
constexpr int OFF_SX  = OFF_H + 2 * HPLANE;    // 156672 (MODE 0 only): 8192 B
constexpr int OFF_W0S = OFF_SX + 8192;
constexpr int OFF_BRS = OFF_W0S + 2048;
constexpr int REC_SM  = OFF_BRS + 2048;        // 168960

constexpr int OFF_AH  = 139264;                // proj: A plane 128*272
constexpr int APLANE  = 128 * WROW;            // 34816
constexpr int OFF_PBR = OFF_AH + APLANE;       // proj bias, 512 floats
constexpr int PROJ_SM = OFF_PBR + 2048;        // 176128

// ---------------- device scratch (static globals; no allocation) ---------------
__device__ __half g_hh [(size_t)T_ * S_ * H_];   // [t*S+s][j]    64 MiB
__device__ __half g_xph[(size_t)T_ * S_ * G4H];  // [t*S+s][4j+g] 256 MiB
__device__ float g_xl1[S_ * G1_];
__device__ float g_h1[S_ * G1_];
__device__ float g_xl2[S_ * G2_];
__device__ float g_h2[S_ * G2_];
__device__ float g_dis[N_];
__device__ int   g_is64;

// ---------------- helpers -------------------------------------------------------
DINLINE float tanhfast(float x) {
    float y;
    asm("tanh.approx.f32 %0, %1;" : "=f"(y) : "f"(x));
    return y;
}

DINLINE u32 smem_u32(const void* p) {
    u32 a;
    asm("{ .reg .u64 t; cvta.to.shared.u64 t, %1; cvt.u32.u64 %0, t; }" : "=r"(a) : "l"(p));
    return a;
}

DINLINE void mma_f16(float* D, const u32* A, u32 b0, u32 b1) {
    asm("mma.sync.aligned.m16n8k16.row.col.f32.f16.f16.f32 "
        "{%0,%1,%2,%3},{%4,%5,%6,%7},{%8,%9},{%0,%1,%2,%3};"
        : "+f"(D[0]), "+f"(D[1]), "+f"(D[2]), "+f"(D[3])
        : "r"(A[0]), "r"(A[1]), "r"(A[2]), "r"(A[3]), "r"(b0), "r"(b1));
}

#define LDSM4(R, ADDR) \
    asm volatile("ldmatrix.sync.aligned.m8n8.x4.shared.b16 {%0,%1,%2,%3},[%4];" \
        : "=r"((R)[0]), "=r"((R)[1]), "=r"((R)[2]), "=r"((R)[3]) : "r"(ADDR))

DINLINE u32 packh(float a, float b) {
    __half2 h = __floats2half2_rn(a, b);
    return *(u32*)&h;
}

DINLINE int edge_at(const void* p, int is64, int idx) {
    return is64 ? (int)((const long long*)p)[idx] : ((const int*)p)[idx];
}

// inline weight image build: fp32 [4H][H] (gate-major) -> SMEM fp16 rows (4j+g)
DINLINE void build_w_image(char* sm, const float* __restrict__ w, int tid, int nthr) {
    for (int i = tid; i < 512 * 64; i += nthr) {
        int colp = i >> 6, kp = i & 63;
        int j = colp >> 2, g = colp & 3;
        float2 wv = *(const float2*)(w + (g * H_ + j) * H_ + 2 * kp);
        *(u32*)(sm + OFF_W + colp * WROW + kp * 4) = packh(wv.x, wv.y);
    }
}

// ---------------- fused edge prep: dtype detect + degree + rsqrt ----------------
__global__ void k_edge_prep(const void* __restrict__ ei) {
    __shared__ float sdeg[N_];
    __shared__ int nz;
    const int tid = threadIdx.x;   // 512 threads
    if (tid == 0) nz = 0;
    sdeg[tid] = 1.0f;              // self-loop
    __syncthreads();
    const int* ei32 = (const int*)ei;
    int acc = 0;
    for (int i = 1 + 2 * tid; i < 2 * E_; i += 1024) acc |= ei32[i];
    if (acc) atomicOr(&nz, 1);
    __syncthreads();
    int is64 = (nz == 0) ? 1 : 0;
    if (tid == 0) g_is64 = is64;
    for (int e = tid; e < E_; e += 512)
        atomicAdd(&sdeg[edge_at(ei, is64, E_ + e)], 1.0f);
    __syncthreads();
    g_dis[tid] = rsqrtf(sdeg[tid]);
}

// ---------------- gate fold: shuffle, input add, activations, h write ------------
template <int MODE>
DINLINE void gate_fold(float* D, float& c_ref, char* sm, bool evn,
                       int myrow, int j, int t, int hw_off, uint2 xq) {
    float sv0 = evn ? D[2] : D[0];
    float rr0 = __shfl_xor_sync(0xffffffffu, sv0, 1);
    float sv1 = evn ? D[3] : D[1];
    float rr1 = __shfl_xor_sync(0xffffffffu, sv1, 1);
    float pi = evn ? D[0] : rr0;
    float pf = evn ? D[1] : rr1;
    float pg = evn ? rr0 : D[2];
    float po = evn ? rr1 : D[3];

    if (MODE == 1) {
        float2 fa = __half22float2(*(__half2*)&xq.x);
        float2 fb = __half22float2(*(__half2*)&xq.y);
        pi += fa.x; pf += fa.y; pg += fb.x; po += fb.y;
    } else {
        float xv = ((const float*)(sm + OFF_SX))[t * 32 + myrow];
        float4 w4 = ((const float4*)(sm + OFF_W0S))[j];
        float4 b4 = ((const float4*)(sm + OFF_BRS))[j];
        pi += xv * w4.x + b4.x;
        pf += xv * w4.y + b4.y;
        pg += xv * w4.z + b4.z;
        po += xv * w4.w + b4.w;
    }

    float si = fmaf(tanhfast(0.5f * pi), 0.5f, 0.5f);
    float sf = fmaf(tanhfast(0.5f * pf), 0.5f, 0.5f);
    float so = fmaf(tanhfast(0.5f * po), 0.5f, 0.5f);
    float cn = sf * c_ref + si * tanhfast(pg);
    c_ref = cn;
    float hv = so * tanhfast(cn);

    *(__half*)(sm + hw_off + myrow * WROW + j * 2) = __float2half_rn(hv);
}

// ---------------- tensor-core LSTM recurrence ------------------------------------
// 512 threads, 16 warps. Warp w owns gate-cols [32w, 32w+32) for BOTH m-tiles;
// B fragments resident in 64 regs, loaded once. Per-mt xp prefetch (transient).
// Weights converted fp32 -> fp16 SMEM image in the prologue (no prep kernel).
template <int MODE, int WRITE_ALL>
__global__ void __launch_bounds__(512, 1) rec_mma(
    const float* __restrict__ x,               // MODE 0
    const float* __restrict__ whh,             // fp32 [4H][H], gate-major
    const float* __restrict__ w0,              // MODE 0: w_ih0 [4H][1]
    const float* __restrict__ bi0,             // MODE 0
    const float* __restrict__ bh0)             // MODE 0
{
    extern __shared__ __align__(16) char sm[];
    const u32 sbase = smem_u32(sm);

    const int tid = threadIdx.x, wid = tid >> 5, lane = tid & 31;
    const int grp = lane >> 2, tid4 = lane & 3;
    const bool evn = (tid4 & 1) == 0;
    const int cw = wid;                        // 32-col group
    const int s0 = blockIdx.x * 32;

    build_w_image(sm, whh, tid, 512);
    for (int i = tid; i < HPLANE / 4; i += 512)       // zero plane 0
        ((u32*)(sm + OFF_H))[i] = 0;
    if (MODE == 0) {
        float* sx = (float*)(sm + OFF_SX);
        for (int i = tid; i < 64 * 32; i += 512) {
            int t = i >> 5, m = i & 31;
            int s = s0 + m;
            sx[i] = x[(s >> 9) * (T_ * N_) + t * N_ + (s & (N_ - 1))];
        }
        if (tid < 512) {
            int j = tid >> 2, g = tid & 3;
            ((float*)(sm + OFF_W0S))[tid] = w0[g * H_ + j];
            ((float*)(sm + OFF_BRS))[tid] = bi0[g * H_ + j] + bh0[g * H_ + j];
        }
    }
    __syncthreads();

    const int qa = lane >> 3;
    const int a_loff = ((lane & 7) + (qa & 1) * 8) * WROW + ((qa >> 1) * 8) * 2;
    const int b_loff = (lane & 7) * WROW + qa * 16;
    const int rowoff = evn ? grp : grp + 8;

    // resident B fragments: 4 n-tiles x 8 ks x 2 regs = 64 regs
    u32 breg[4][8][2];
#pragma unroll
    for (int nt = 0; nt < 4; nt++) {
        const int n0 = cw * 32 + nt * 8;
#pragma unroll
        for (int kc = 0; kc < 4; kc++) {
            u32 r[4];
            LDSM4(r, sbase + OFF_W + n0 * WROW + b_loff + kc * 64);
            breg[nt][kc * 2][0] = r[0]; breg[nt][kc * 2][1] = r[1];
            breg[nt][kc * 2 + 1][0] = r[2]; breg[nt][kc * 2 + 1][1] = r[3];
        }
    }

    float c_st[8];
#pragma unroll
    for (int q = 0; q < 8; q++) c_st[q] = 0.0f;

    for (int t = 0; t < T_; t++) {
        const int rb = t & 1, wb = rb ^ 1;
        const int hw_off = OFF_H + wb * HPLANE;

#pragma unroll
        for (int mt = 0; mt < 2; mt++) {
            const int myrow = mt * 16 + rowoff;

            // prefetch xp for this m-tile (transient; self-consumed)
            uint2 xq[4];
            if (MODE == 1) {
                const __half* xpb = g_xph + ((size_t)t * S_ + s0 + myrow) * G4H
                                    + cw * 32 + (tid4 >> 1) * 4;
#pragma unroll
                for (int nt = 0; nt < 4; nt++)
                    xq[nt] = *(const uint2*)(xpb + nt * 8);
            }

            float D[4][4];
#pragma unroll
            for (int nt = 0; nt < 4; nt++)
#pragma unroll
                for (int q = 0; q < 4; q++) D[nt][q] = 0.0f;

            const u32 a_base = sbase + OFF_H + rb * HPLANE + mt * 16 * WROW + a_loff;
#pragma unroll
            for (int kchunk = 0; kchunk < 2; kchunk++) {
                u32 ahi[4][4];
#pragma unroll
                for (int k4 = 0; k4 < 4; k4++)
                    LDSM4(ahi[k4], a_base + (kchunk * 4 + k4) * 32);
#pragma unroll
                for (int nt = 0; nt < 4; nt++)
#pragma unroll
                    for (int k4 = 0; k4 < 4; k4++)
                        mma_f16(D[nt], ahi[k4],
                                breg[nt][kchunk * 4 + k4][0],
                                breg[nt][kchunk * 4 + k4][1]);
            }

#pragma unroll
            for (int nt = 0; nt < 4; nt++)
                gate_fold<MODE>(D[nt], c_st[mt * 4 + nt], sm, evn, myrow,
                                cw * 8 + nt * 2 + (tid4 >> 1), t, hw_off, xq[nt]);
        }

        __syncthreads();   // h(wb) complete; A-reads of rb done

        if (WRITE_ALL || t == T_ - 1) {
            for (int i = tid; i < 32 * 32; i += 512) {
                int r = i >> 5, jp4 = i & 31;
                uint2 v = *(const uint2*)(sm + hw_off + r * WROW + jp4 * 8);
                *(uint2*)&g_hh[((size_t)t * S_ + s0 + r) * H_ + jp4 * 4] = v;
            }
        }
    }
}

// ---------------- tensor-core input projection (persistent, 512 thr) -------------
// Warp w owns cols [32w, 32w+32) with resident B fragments; loops over 8 m-tiles.
// Weights + bias converted/combined inline in the prologue.
__global__ void __launch_bounds__(512, 1) proj_mma(
    const float* __restrict__ wih,             // fp32 [4H][H], gate-major
    const float* __restrict__ bi,
    const float* __restrict__ bh)
{
    extern __shared__ __align__(16) char sm[];
    const u32 sbase = smem_u32(sm);

    const int tid = threadIdx.x, wid = tid >> 5, lane = tid & 31;
    const int grp = lane >> 2, tid4 = lane & 3;
    const int cw = wid;

    build_w_image(sm, wih, tid, 512);
    if (tid < 512) {
        int j = tid >> 2, g = tid & 3;
        ((float*)(sm + OFF_PBR))[tid] = bi[g * H_ + j] + bh[g * H_ + j];
    }
    __syncthreads();

    const int qa = lane >> 3;
    const int a_loff = ((lane & 7) + (qa & 1) * 8) * WROW + ((qa >> 1) * 8) * 2;
    const int b_loff = (lane & 7) * WROW + qa * 16;

    // resident B fragments + bias
    u32 breg[4][8][2];
    float2 bbv[4];
#pragma unroll
    for (int nt = 0; nt < 4; nt++) {
        const int n0 = cw * 32 + nt * 8;
#pragma unroll
        for (int kc = 0; kc < 4; kc++) {
            u32 r[4];
            LDSM4(r, sbase + OFF_W + n0 * WROW + b_loff + kc * 64);
            breg[nt][kc * 2][0] = r[0]; breg[nt][kc * 2][1] = r[1];
            breg[nt][kc * 2 + 1][0] = r[2]; breg[nt][kc * 2 + 1][1] = r[3];
        }
        bbv[nt] = *(const float2*)((const float*)(sm + OFF_PBR) + n0 + tid4 * 2);
    }

    const int ntiles = (T_ * S_) / 128;   // 2048
    for (int rt = blockIdx.x; rt < ntiles; rt += gridDim.x) {
        __syncthreads();
        const u32* src = (const u32*)(g_hh + (size_t)rt * 128 * H_);
        for (int i = tid; i < 128 * 64; i += 512) {
            int row = i >> 6, kp = i & 63;
            *(u32*)(sm + OFF_AH + row * WROW + kp * 4) = src[i];
        }
        __syncthreads();

#pragma unroll 1
        for (int mt = 0; mt < 8; mt++) {
            u32 ahi[8][4];
            const u32 abase = sbase + OFF_AH + mt * 16 * WROW + a_loff;
#pragma unroll
            for (int ks = 0; ks < 8; ks++) LDSM4(ahi[ks], abase + ks * 32);

#pragma unroll
            for (int nt = 0; nt < 4; nt++) {
                const int n0 = cw * 32 + nt * 8;
                float D[4] = {bbv[nt].x, bbv[nt].y, bbv[nt].x, bbv[nt].y};
#pragma unroll
                for (int ks = 0; ks < 8; ks++)
                    mma_f16(D, ahi[ks], breg[nt][ks][0], breg[nt][ks][1]);

                size_t rowA = ((size_t)rt * 128 + mt * 16 + grp) * G4H;
                size_t rowB = rowA + 8 * G4H;
                *(u32*)&g_xph[rowA + n0 + tid4 * 2] = packh(D[0], D[1]);
                *(u32*)&g_xph[rowB + n0 + tid4 * 2] = packh(D[2], D[3]);
            }
        }
    }
}

// ---------------- GCN -------------------------------------------------------------
__global__ void k_lin1(const float* __restrict__ w, const float* __restrict__ bias) {
    __shared__ float fr[8][H_];
    int r0 = blockIdx.x * 8, tid = threadIdx.x;   // 512 blocks, 128 thr
    for (int i = tid; i < 8 * H_; i += 128) {
        int r = i >> 7, k = i & 127;
        fr[r][k] = __half2float(g_hh[((size_t)(T_ - 1) * S_ + r0 + r) * H_ + k]);
    }
    __syncthreads();
    const float* wr = w + tid * H_;
    float acc[8] = {0, 0, 0, 0, 0, 0, 0, 0};
#pragma unroll 4
    for (int k = 0; k < H_; k++) {
        float wk = wr[k];
#pragma unroll
        for (int r = 0; r < 8; r++) acc[r] = fmaf(fr[r][k], wk, acc[r]);
    }
    float bv = bias[tid];
#pragma unroll
    for (int r = 0; r < 8; r++) {
        g_xl1[(r0 + r) * G1_ + tid] = acc[r];
        float d = g_dis[(r0 + r) & (N_ - 1)];
        g_h1[(r0 + r) * G1_ + tid] = bv + acc[r] * d * d;
    }
}

__global__ void k_lin2(const float* __restrict__ w, const float* __restrict__ bias) {
    __shared__ float fr[8][G1_];
    int r0 = blockIdx.x * 8, tid = threadIdx.x;   // 512 blocks, 64 thr
    for (int i = tid; i < 8 * G1_; i += 64) {
        int r = i >> 7, k = i & 127;
        fr[r][k] = fmaxf(g_h1[(r0 + r) * G1_ + k], 0.0f);
    }
    __syncthreads();
    const float* wr = w + tid * G1_;
    float acc[8] = {0, 0, 0, 0, 0, 0, 0, 0};
#pragma unroll 4
    for (int k = 0; k < G1_; k++) {
        float wk = wr[k];
#pragma unroll
        for (int r = 0; r < 8; r++) acc[r] = fmaf(fr[r][k], wk, acc[r]);
    }
    float bv = bias[tid];
#pragma unroll
    for (int r = 0; r < 8; r++) {
        g_xl2[(r0 + r) * G2_ + tid] = acc[r];
        float d = g_dis[(r0 + r) & (N_ - 1)];
        g_h2[(r0 + r) * G2_ + tid] = bv + acc[r] * d * d;
    }
}

template <int Gd>
__global__ void k_agg_edge(const void* __restrict__ ei) {
    constexpr int G4 = Gd / 4;
    const float* xl = (Gd == G1_) ? g_xl1 : g_xl2;
    float* outb     = (Gd == G1_) ? g_h1  : g_h2;
    int i = blockIdx.x * blockDim.x + threadIdx.x;
    constexpr int per = B_ * G4;
    if (i >= E_ * per) return;
    int e = i / per;
    int r = i - e * per;
    int b = r / G4;
    int g4 = r - b * G4;
    int is64 = g_is64;
    int src = edge_at(ei, is64, e);
    int dst = edge_at(ei, is64, E_ + e);
    float norm = g_dis[src] * g_dis[dst];
    float4 v = *(const float4*)&xl[(b * N_ + src) * Gd + g4 * 4];
    float* o = &outb[(b * N_ + dst) * Gd + g4 * 4];
    atomicAdd(o + 0, v.x * norm);
    atomicAdd(o + 1, v.y * norm);
    atomicAdd(o + 2, v.z * norm);
    atomicAdd(o + 3, v.w * norm);
}

__global__ void k_final(const float* __restrict__ cls_w,
                        const float* __restrict__ cls_b,
                        float* __restrict__ out) {
    int b = blockIdx.x, tid = threadIdx.x;
    __shared__ float red[256];
    float a = 0.0f;
    for (int i = tid; i < N_ * G2_; i += 256) {
        int g = i & (G2_ - 1);
        a = fmaf(fmaxf(g_h2[b * (N_ * G2_) + i], 0.0f), cls_w[g], a);
    }
    red[tid] = a;
    __syncthreads();
    for (int s = 128; s > 0; s >>= 1) {
        if (tid < s) red[tid] += red[tid + s];
        __syncthreads();
    }
    if (tid == 0) out[b] = red[0] * (1.0f / N_) + cls_b[0];
}

// ---------------- launch -----------------------------------------------------------
extern "C" void kernel_launch(void* const* d_in, const int* in_sizes, int n_in,
                              void* d_out, int out_size) {
    const float* x      = (const float*)d_in[0];
    const void*  ei     = d_in[1];
    const float* w_ih0  = (const float*)d_in[2];
    const float* w_hh0  = (const float*)d_in[3];
    const float* b_ih0  = (const float*)d_in[4];
    const float* b_hh0  = (const float*)d_in[5];
    const float* w_ih1  = (const float*)d_in[6];
    const float* w_hh1  = (const float*)d_in[7];
    const float* b_ih1  = (const float*)d_in[8];
    const float* b_hh1  = (const float*)d_in[9];
    const float* w_ih2  = (const float*)d_in[10];
    const float* w_hh2  = (const float*)d_in[11];
    const float* b_ih2  = (const float*)d_in[12];
    const float* b_hh2  = (const float*)d_in[13];
    const float* gcn1_w = (const float*)d_in[14];
    const float* gcn1_b = (const float*)d_in[15];
    const float* gcn2_w = (const float*)d_in[16];
    const float* gcn2_b = (const float*)d_in[17];
    const float* cls_w  = (const float*)d_in[18];
    const float* cls_b  = (const float*)d_in[19];
    float* out = (float*)d_out;

    cudaFuncSetAttribute(rec_mma<0, 1>, cudaFuncAttributeMaxDynamicSharedMemorySize, REC_SM);
    cudaFuncSetAttribute(rec_mma<1, 1>, cudaFuncAttributeMaxDynamicSharedMemorySize, REC_SM);
    cudaFuncSetAttribute(rec_mma<1, 0>, cudaFuncAttributeMaxDynamicSharedMemorySize, REC_SM);
    cudaFuncSetAttribute(proj_mma, cudaFuncAttributeMaxDynamicSharedMemorySize, PROJ_SM);

    const int RB = S_ / 32;   // 128 blocks

    k_edge_prep<<<1, 512>>>(ei);

    // layer 0
    rec_mma<0, 1><<<RB, 512, REC_SM>>>(x, w_hh0, w_ih0, b_ih0, b_hh0);
    // layer 1
    proj_mma<<<148, 512, PROJ_SM>>>(w_ih1, b_ih1, b_hh1);
    rec_mma<1, 1><<<RB, 512, REC_SM>>>(nullptr, w_hh1, nullptr, nullptr, nullptr);
    // layer 2
    proj_mma<<<148, 512, PROJ_SM>>>(w_ih2, b_ih2, b_hh2);
    rec_mma<1, 0><<<RB, 512, REC_SM>>>(nullptr, w_hh2, nullptr, nullptr, nullptr);

    // GCN
    k_lin1<<<S_ / 8, 128>>>(gcn1_w, gcn1_b);
    k_agg_edge<G1_><<<(E_ * B_ * (G1_ / 4) + 255) / 256, 256>>>(ei);
    k_lin2<<<S_ / 8, 64>>>(gcn2_w, gcn2_b);
    k_agg_edge<G2_><<<(E_ * B_ * (G2_ / 4) + 255) / 256, 256>>>(ei);
    k_final<<<B_, 256>>>(cls_w, cls_b, out);
}

// round 17
// speedup vs baseline: 1.1054x; 1.0574x over previous
#include <cuda_runtime.h>
#include <cuda_fp16.h>

#define DINLINE __device__ __forceinline__
typedef unsigned int u32;
typedef unsigned short u16;

constexpr int B_ = 8, T_ = 64, N_ = 512, H_ = 128, E_ = 8192;
constexpr int S_ = B_ * N_;       // 4096 sequences
constexpr int G1_ = 128, G2_ = 64;
constexpr int G4H = 4 * H_;       // 512 gate rows

// ---------------- SMEM layout (byte offsets) -----------------------------------
constexpr int WROW    = 272;                   // 136 fp16 per row (128 + 8 pad)
constexpr int OFF_W   = 0;                     // 512*272 = 139264
constexpr int OFF_H   = 139264;                // h planes (2 x 32 x 272), fp16
constexpr int HPLANE  = 32 * WROW;             // 8704
constexpr int OFF_SX  = OFF_H + 2 * HPLANE;    // 156672
// MODE 1: xp double-buffer stage lives at OFF_SX (2 x 32 rows x 1040 B)
constexpr int XPSROW  = 1040;                  // 1024 B data + 16 B skew
constexpr int XPBUF   = 32 * XPSROW;           // 33280
// MODE 0 reuse of the same region:
constexpr int OFF_W0S = OFF_SX + 8192;
constexpr int OFF_BRS = OFF_W0S + 2048;
constexpr int REC_SM  = OFF_SX + 2 * XPBUF;    // 223232

constexpr int OFF_AH  = 139264;                // proj: A plane 128*272
constexpr int APLANE  = 128 * WROW;            // 34816
constexpr int OFF_PBR = OFF_AH + APLANE;       // proj bias, 512 floats
constexpr int PROJ_SM = OFF_PBR + 2048;        // 176128

// ---------------- device scratch (static globals; no allocation) ---------------
__device__ __half g_hh [(size_t)T_ * S_ * H_];   // [t*S+s][j]    64 MiB
__device__ __half g_xph[(size_t)T_ * S_ * G4H];  // [t*S+s][4j+g] 256 MiB
__device__ float g_xl1[S_ * G1_];
__device__ float g_h1[S_ * G1_];
__device__ float g_xl2[S_ * G2_];
__device__ float g_h2[S_ * G2_];
__device__ float g_dis[N_];
__device__ int   g_is64;

// ---------------- helpers -------------------------------------------------------
DINLINE float tanhfast(float x) {
    float y;
    asm("tanh.approx.f32 %0, %1;" : "=f"(y) : "f"(x));
    return y;
}

DINLINE u32 smem_u32(const void* p) {
    u32 a;
    asm("{ .reg .u64 t; cvta.to.shared.u64 t, %1; cvt.u32.u64 %0, t; }" : "=r"(a) : "l"(p));
    return a;
}

DINLINE void mma_f16(float* D, const u32* A, u32 b0, u32 b1) {
    asm("mma.sync.aligned.m16n8k16.row.col.f32.f16.f16.f32 "
        "{%0,%1,%2,%3},{%4,%5,%6,%7},{%8,%9},{%0,%1,%2,%3};"
        : "+f"(D[0]), "+f"(D[1]), "+f"(D[2]), "+f"(D[3])
        : "r"(A[0]), "r"(A[1]), "r"(A[2]), "r"(A[3]), "r"(b0), "r"(b1));
}

#define LDSM4(R, ADDR) \
    asm volatile("ldmatrix.sync.aligned.m8n8.x4.shared.b16 {%0,%1,%2,%3},[%4];" \
        : "=r"((R)[0]), "=r"((R)[1]), "=r"((R)[2]), "=r"((R)[3]) : "r"(ADDR))

DINLINE void cp_async16(u32 dst, const void* src) {
    asm volatile("cp.async.cg.shared.global [%0], [%1], 16;" :: "r"(dst), "l"(src) : "memory");
}
#define CP_COMMIT() asm volatile("cp.async.commit_group;" ::: "memory")
#define CP_WAIT0()  asm volatile("cp.async.wait_group 0;" ::: "memory")

DINLINE u32 packh(float a, float b) {
    __half2 h = __floats2half2_rn(a, b);
    return *(u32*)&h;
}

DINLINE int edge_at(const void* p, int is64, int idx) {
    return is64 ? (int)((const long long*)p)[idx] : ((const int*)p)[idx];
}

// inline weight image build: fp32 [4H][H] (gate-major) -> SMEM fp16 rows (4j+g)
DINLINE void build_w_image(char* sm, const float* __restrict__ w, int tid, int nthr) {
    for (int i = tid; i < 512 * 64; i += nthr) {
        int colp = i >> 6, kp = i & 63;
        int j = colp >> 2, g = colp & 3;
        float2 wv = *(const float2*)(w + (g * H_ + j) * H_ + 2 * kp);
        *(u32*)(sm + OFF_W + colp * WROW + kp * 4) = packh(wv.x, wv.y);
    }
}

// ---------------- fused edge prep: dtype detect + degree + rsqrt ----------------
__global__ void k_edge_prep(const void* __restrict__ ei) {
    __shared__ float sdeg[N_];
    __shared__ int nz;
    const int tid = threadIdx.x;   // 512 threads
    if (tid == 0) nz = 0;
    sdeg[tid] = 1.0f;              // self-loop
    __syncthreads();
    const int* ei32 = (const int*)ei;
    int acc = 0;
    for (int i = 1 + 2 * tid; i < 2 * E_; i += 1024) acc |= ei32[i];
    if (acc) atomicOr(&nz, 1);
    __syncthreads();
    int is64 = (nz == 0) ? 1 : 0;
    if (tid == 0) g_is64 = is64;
    for (int e = tid; e < E_; e += 512)
        atomicAdd(&sdeg[edge_at(ei, is64, E_ + e)], 1.0f);
    __syncthreads();
    g_dis[tid] = rsqrtf(sdeg[tid]);
}

// ---------------- gate fold: shuffle, input add, activations, h write ------------
// MODE 1: xp comes from the SMEM stage at xp_addr (+nt*16 per n-tile).
template <int MODE>
DINLINE void gate_fold(float* D, float& c_ref, char* sm, bool evn,
                       int myrow, int j, int t, int hw_off, u32 xp_off) {
    float sv0 = evn ? D[2] : D[0];
    float rr0 = __shfl_xor_sync(0xffffffffu, sv0, 1);
    float sv1 = evn ? D[3] : D[1];
    float rr1 = __shfl_xor_sync(0xffffffffu, sv1, 1);
    float pi = evn ? D[0] : rr0;
    float pf = evn ? D[1] : rr1;
    float pg = evn ? rr0 : D[2];
    float po = evn ? rr1 : D[3];

    if (MODE == 1) {
        uint2 xq = *(const uint2*)(sm + xp_off);
        float2 fa = __half22float2(*(__half2*)&xq.x);
        float2 fb = __half22float2(*(__half2*)&xq.y);
        pi += fa.x; pf += fa.y; pg += fb.x; po += fb.y;
    } else {
        float xv = ((const float*)(sm + OFF_SX))[t * 32 + myrow];
        float4 w4 = ((const float4*)(sm + OFF_W0S))[j];
        float4 b4 = ((const float4*)(sm + OFF_BRS))[j];
        pi += xv * w4.x + b4.x;
        pf += xv * w4.y + b4.y;
        pg += xv * w4.z + b4.z;
        po += xv * w4.w + b4.w;
    }

    float si = fmaf(tanhfast(0.5f * pi), 0.5f, 0.5f);
    float sf = fmaf(tanhfast(0.5f * pf), 0.5f, 0.5f);
    float so = fmaf(tanhfast(0.5f * po), 0.5f, 0.5f);
    float cn = sf * c_ref + si * tanhfast(pg);
    c_ref = cn;
    float hv = so * tanhfast(cn);

    *(__half*)(sm + hw_off + myrow * WROW + j * 2) = __float2half_rn(hv);
}

// ---------------- tensor-core LSTM recurrence ------------------------------------
// 512 threads, 16 warps. Warp w owns gate-cols [32w, 32w+32) for BOTH m-tiles;
// B fragments resident in 64 regs. xp pipelined one step ahead via cp.async.
template <int MODE, int WRITE_ALL>
__global__ void __launch_bounds__(512, 1) rec_mma(
    const float* __restrict__ x,               // MODE 0
    const float* __restrict__ whh,             // fp32 [4H][H], gate-major
    const float* __restrict__ w0,              // MODE 0: w_ih0 [4H][1]
    const float* __restrict__ bi0,             // MODE 0
    const float* __restrict__ bh0)             // MODE 0
{
    extern __shared__ __align__(16) char sm[];
    const u32 sbase = smem_u32(sm);

    const int tid = threadIdx.x, wid = tid >> 5, lane = tid & 31;
    const int grp = lane >> 2, tid4 = lane & 3;
    const bool evn = (tid4 & 1) == 0;
    const int cw = wid;                        // 32-col group
    const int s0 = blockIdx.x * 32;

    // issue xp[0] stage early (MODE 1) so it lands before the loop starts
    if (MODE == 1) {
#pragma unroll
        for (int q = 0; q < 4; q++) {
            int chunk = q * 512 + tid;
            int r = chunk >> 6, c16 = chunk & 63;
            cp_async16(sbase + OFF_SX + r * XPSROW + c16 * 16,
                       g_xph + ((size_t)0 * S_ + s0 + r) * G4H + c16 * 8);
        }
        CP_COMMIT();
    }

    build_w_image(sm, whh, tid, 512);
    for (int i = tid; i < HPLANE / 4; i += 512)       // zero plane 0
        ((u32*)(sm + OFF_H))[i] = 0;
    if (MODE == 0) {
        float* sx = (float*)(sm + OFF_SX);
        for (int i = tid; i < 64 * 32; i += 512) {
            int t = i >> 5, m = i & 31;
            int s = s0 + m;
            sx[i] = x[(s >> 9) * (T_ * N_) + t * N_ + (s & (N_ - 1))];
        }
        if (tid < 512) {
            int j = tid >> 2, g = tid & 3;
            ((float*)(sm + OFF_W0S))[tid] = w0[g * H_ + j];
            ((float*)(sm + OFF_BRS))[tid] = bi0[g * H_ + j] + bh0[g * H_ + j];
        }
    }
    if (MODE == 1) CP_WAIT0();
    __syncthreads();

    const int qa = lane >> 3;
    const int a_loff = ((lane & 7) + (qa & 1) * 8) * WROW + ((qa >> 1) * 8) * 2;
    const int b_loff = (lane & 7) * WROW + qa * 16;
    const int rowoff = evn ? grp : grp + 8;
    // xp stage read offset base (within a buffer): row myrow, col cw*32 + (tid4>>1)*4
    const int xp_loff = (cw * 32 + (tid4 >> 1) * 4) * 2;

    // resident B fragments: 4 n-tiles x 8 ks x 2 regs = 64 regs
    u32 breg[4][8][2];
#pragma unroll
    for (int nt = 0; nt < 4; nt++) {
        const int n0 = cw * 32 + nt * 8;
#pragma unroll
        for (int kc = 0; kc < 4; kc++) {
            u32 r[4];
            LDSM4(r, sbase + OFF_W + n0 * WROW + b_loff + kc * 64);
            breg[nt][kc * 2][0] = r[0]; breg[nt][kc * 2][1] = r[1];
            breg[nt][kc * 2 + 1][0] = r[2]; breg[nt][kc * 2 + 1][1] = r[3];
        }
    }

    float c_st[8];
#pragma unroll
    for (int q = 0; q < 8; q++) c_st[q] = 0.0f;

    for (int t = 0; t < T_; t++) {
        const int rb = t & 1, wb = rb ^ 1;
        const int hw_off = OFF_H + wb * HPLANE;
        const int xbuf_r = OFF_SX + (t & 1) * XPBUF;

        // issue next step's xp stage (lands by end of this step)
        if (MODE == 1 && t + 1 < T_) {
            const int xbuf_w = OFF_SX + ((t + 1) & 1) * XPBUF;
#pragma unroll
            for (int q = 0; q < 4; q++) {
                int chunk = q * 512 + tid;
                int r = chunk >> 6, c16 = chunk & 63;
                cp_async16(sbase + xbuf_w + r * XPSROW + c16 * 16,
                           g_xph + ((size_t)(t + 1) * S_ + s0 + r) * G4H + c16 * 8);
            }
            CP_COMMIT();
        }

#pragma unroll
        for (int mt = 0; mt < 2; mt++) {
            const int myrow = mt * 16 + rowoff;
            const u32 xp_base = xbuf_r + myrow * XPSROW + xp_loff;

            float D[4][4];
#pragma unroll
            for (int nt = 0; nt < 4; nt++)
#pragma unroll
                for (int q = 0; q < 4; q++) D[nt][q] = 0.0f;

            const u32 a_base = sbase + OFF_H + rb * HPLANE + mt * 16 * WROW + a_loff;
#pragma unroll
            for (int kchunk = 0; kchunk < 2; kchunk++) {
                u32 ahi[4][4];
#pragma unroll
                for (int k4 = 0; k4 < 4; k4++)
                    LDSM4(ahi[k4], a_base + (kchunk * 4 + k4) * 32);
#pragma unroll
                for (int nt = 0; nt < 4; nt++)
#pragma unroll
                    for (int k4 = 0; k4 < 4; k4++)
                        mma_f16(D[nt], ahi[k4],
                                breg[nt][kchunk * 4 + k4][0],
                                breg[nt][kchunk * 4 + k4][1]);
            }

#pragma unroll
            for (int nt = 0; nt < 4; nt++)
                gate_fold<MODE>(D[nt], c_st[mt * 4 + nt], sm, evn, myrow,
                                cw * 8 + nt * 2 + (tid4 >> 1), t, hw_off,
                                xp_base + nt * 16);
        }

        if (MODE == 1) CP_WAIT0();   // next step's xp landed
        __syncthreads();             // h(wb) complete; A-reads of rb done; xp visible

        if (WRITE_ALL || t == T_ - 1) {
            for (int i = tid; i < 32 * 32; i += 512) {
                int r = i >> 5, jp4 = i & 31;
                uint2 v = *(const uint2*)(sm + hw_off + r * WROW + jp4 * 8);
                *(uint2*)&g_hh[((size_t)t * S_ + s0 + r) * H_ + jp4 * 4] = v;
            }
        }
    }
}

// ---------------- tensor-core input projection (persistent, 512 thr) -------------
__global__ void __launch_bounds__(512, 1) proj_mma(
    const float* __restrict__ wih,             // fp32 [4H][H], gate-major
    const float* __restrict__ bi,
    const float* __restrict__ bh)
{
    extern __shared__ __align__(16) char sm[];
    const u32 sbase = smem_u32(sm);

    const int tid = threadIdx.x, wid = tid >> 5, lane = tid & 31;
    const int grp = lane >> 2, tid4 = lane & 3;
    const int cw = wid;

    build_w_image(sm, wih, tid, 512);
    if (tid < 512) {
        int j = tid >> 2, g = tid & 3;
        ((float*)(sm + OFF_PBR))[tid] = bi[g * H_ + j] + bh[g * H_ + j];
    }
    __syncthreads();

    const int qa = lane >> 3;
    const int a_loff = ((lane & 7) + (qa & 1) * 8) * WROW + ((qa >> 1) * 8) * 2;
    const int b_loff = (lane & 7) * WROW + qa * 16;

    // resident B fragments + bias
    u32 breg[4][8][2];
    float2 bbv[4];
#pragma unroll
    for (int nt = 0; nt < 4; nt++) {
        const int n0 = cw * 32 + nt * 8;
#pragma unroll
        for (int kc = 0; kc < 4; kc++) {
            u32 r[4];
            LDSM4(r, sbase + OFF_W + n0 * WROW + b_loff + kc * 64);
            breg[nt][kc * 2][0] = r[0]; breg[nt][kc * 2][1] = r[1];
            breg[nt][kc * 2 + 1][0] = r[2]; breg[nt][kc * 2 + 1][1] = r[3];
        }
        bbv[nt] = *(const float2*)((const float*)(sm + OFF_PBR) + n0 + tid4 * 2);
    }

    const int ntiles = (T_ * S_) / 128;   // 2048
    for (int rt = blockIdx.x; rt < ntiles; rt += gridDim.x) {
        __syncthreads();
        const u32* src = (const u32*)(g_hh + (size_t)rt * 128 * H_);
        for (int i = tid; i < 128 * 64; i += 512) {
            int row = i >> 6, kp = i & 63;
            *(u32*)(sm + OFF_AH + row * WROW + kp * 4) = src[i];
        }
        __syncthreads();

#pragma unroll 1
        for (int mt = 0; mt < 8; mt++) {
            u32 ahi[8][4];
            const u32 abase = sbase + OFF_AH + mt * 16 * WROW + a_loff;
#pragma unroll
            for (int ks = 0; ks < 8; ks++) LDSM4(ahi[ks], abase + ks * 32);

#pragma unroll
            for (int nt = 0; nt < 4; nt++) {
                const int n0 = cw * 32 + nt * 8;
                float D[4] = {bbv[nt].x, bbv[nt].y, bbv[nt].x, bbv[nt].y};
#pragma unroll
                for (int ks = 0; ks < 8; ks++)
                    mma_f16(D, ahi[ks], breg[nt][ks][0], breg[nt][ks][1]);

                size_t rowA = ((size_t)rt * 128 + mt * 16 + grp) * G4H;
                size_t rowB = rowA + 8 * G4H;
                *(u32*)&g_xph[rowA + n0 + tid4 * 2] = packh(D[0], D[1]);
                *(u32*)&g_xph[rowB + n0 + tid4 * 2] = packh(D[2], D[3]);
            }
        }
    }
}

// ---------------- GCN -------------------------------------------------------------
__global__ void k_lin1(const float* __restrict__ w, const float* __restrict__ bias) {
    __shared__ float fr[8][H_];
    int r0 = blockIdx.x * 8, tid = threadIdx.x;   // 512 blocks, 128 thr
    for (int i = tid; i < 8 * H_; i += 128) {
        int r = i >> 7, k = i & 127;
        fr[r][k] = __half2float(g_hh[((size_t)(T_ - 1) * S_ + r0 + r) * H_ + k]);
    }
    __syncthreads();
    const float* wr = w + tid * H_;
    float acc[8] = {0, 0, 0, 0, 0, 0, 0, 0};
#pragma unroll 4
    for (int k = 0; k < H_; k++) {
        float wk = wr[k];
#pragma unroll
        for (int r = 0; r < 8; r++) acc[r] = fmaf(fr[r][k], wk, acc[r]);
    }
    float bv = bias[tid];
#pragma unroll
    for (int r = 0; r < 8; r++) {
        g_xl1[(r0 + r) * G1_ + tid] = acc[r];
        float d = g_dis[(r0 + r) & (N_ - 1)];
        g_h1[(r0 + r) * G1_ + tid] = bv + acc[r] * d * d;
    }
}

__global__ void k_lin2(const float* __restrict__ w, const float* __restrict__ bias) {
    __shared__ float fr[8][G1_];
    int r0 = blockIdx.x * 8, tid = threadIdx.x;   // 512 blocks, 64 thr
    for (int i = tid; i < 8 * G1_; i += 64) {
        int r = i >> 7, k = i & 127;
        fr[r][k] = fmaxf(g_h1[(r0 + r) * G1_ + k], 0.0f);
    }
    __syncthreads();
    const float* wr = w + tid * G1_;
    float acc[8] = {0, 0, 0, 0, 0, 0, 0, 0};
#pragma unroll 4
    for (int k = 0; k < G1_; k++) {
        float wk = wr[k];
#pragma unroll
        for (int r = 0; r < 8; r++) acc[r] = fmaf(fr[r][k], wk, acc[r]);
    }
    float bv = bias[tid];
#pragma unroll
    for (int r = 0; r < 8; r++) {
        g_xl2[(r0 + r) * G2_ + tid] = acc[r];
        float d = g_dis[(r0 + r) & (N_ - 1)];
        g_h2[(r0 + r) * G2_ + tid] = bv + acc[r] * d * d;
    }
}

template <int Gd>
__global__ void k_agg_edge(const void* __restrict__ ei) {
    constexpr int G4 = Gd / 4;
    const float* xl = (Gd == G1_) ? g_xl1 : g_xl2;
    float* outb     = (Gd == G1_) ? g_h1  : g_h2;
    int i = blockIdx.x * blockDim.x + threadIdx.x;
    constexpr int per = B_ * G4;
    if (i >= E_ * per) return;
    int e = i / per;
    int r = i - e * per;
    int b = r / G4;
    int g4 = r - b * G4;
    int is64 = g_is64;
    int src = edge_at(ei, is64, e);
    int dst = edge_at(ei, is64, E_ + e);
    float norm = g_dis[src] * g_dis[dst];
    float4 v = *(const float4*)&xl[(b * N_ + src) * Gd + g4 * 4];
    float* o = &outb[(b * N_ + dst) * Gd + g4 * 4];
    atomicAdd(o + 0, v.x * norm);
    atomicAdd(o + 1, v.y * norm);
    atomicAdd(o + 2, v.z * norm);
    atomicAdd(o + 3, v.w * norm);
}

__global__ void k_final(const float* __restrict__ cls_w,
                        const float* __restrict__ cls_b,
                        float* __restrict__ out) {
    int b = blockIdx.x, tid = threadIdx.x;
    __shared__ float red[256];
    float a = 0.0f;
    for (int i = tid; i < N_ * G2_; i += 256) {
        int g = i & (G2_ - 1);
        a = fmaf(fmaxf(g_h2[b * (N_ * G2_) + i], 0.0f), cls_w[g], a);
    }
    red[tid] = a;
    __syncthreads();
    for (int s = 128; s > 0; s >>= 1) {
        if (tid < s) red[tid] += red[tid + s];
        __syncthreads();
    }
    if (tid == 0) out[b] = red[0] * (1.0f / N_) + cls_b[0];
}

// ---------------- launch -----------------------------------------------------------
extern "C" void kernel_launch(void* const* d_in, const int* in_sizes, int n_in,
                              void* d_out, int out_size) {
    const float* x      = (const float*)d_in[0];
    const void*  ei     = d_in[1];
    const float* w_ih0  = (const float*)d_in[2];
    const float* w_hh0  = (const float*)d_in[3];
    const float* b_ih0  = (const float*)d_in[4];
    const float* b_hh0  = (const float*)d_in[5];
    const float* w_ih1  = (const float*)d_in[6];
    const float* w_hh1  = (const float*)d_in[7];
    const float* b_ih1  = (const float*)d_in[8];
    const float* b_hh1  = (const float*)d_in[9];
    const float* w_ih2  = (const float*)d_in[10];
    const float* w_hh2  = (const float*)d_in[11];
    const float* b_ih2  = (const float*)d_in[12];
    const float* b_hh2  = (const float*)d_in[13];
    const float* gcn1_w = (const float*)d_in[14];
    const float* gcn1_b = (const float*)d_in[15];
    const float* gcn2_w = (const float*)d_in[16];
    const float* gcn2_b = (const float*)d_in[17];
    const float* cls_w  = (const float*)d_in[18];
    const float* cls_b  = (const float*)d_in[19];
    float* out = (float*)d_out;

    cudaFuncSetAttribute(rec_mma<0, 1>, cudaFuncAttributeMaxDynamicSharedMemorySize, REC_SM);
    cudaFuncSetAttribute(rec_mma<1, 1>, cudaFuncAttributeMaxDynamicSharedMemorySize, REC_SM);
    cudaFuncSetAttribute(rec_mma<1, 0>, cudaFuncAttributeMaxDynamicSharedMemorySize, REC_SM);
    cudaFuncSetAttribute(proj_mma, cudaFuncAttributeMaxDynamicSharedMemorySize, PROJ_SM);

    const int RB = S_ / 32;   // 128 blocks

    k_edge_prep<<<1, 512>>>(ei);

    // layer 0
    rec_mma<0, 1><<<RB, 512, REC_SM>>>(x, w_hh0, w_ih0, b_ih0, b_hh0);
    // layer 1
    proj_mma<<<148, 512, PROJ_SM>>>(w_ih1, b_ih1, b_hh1);
    rec_mma<1, 1><<<RB, 512, REC_SM>>>(nullptr, w_hh1, nullptr, nullptr, nullptr);
    // layer 2
    proj_mma<<<148, 512, PROJ_SM>>>(w_ih2, b_ih2, b_hh2);
    rec_mma<1, 0><<<RB, 512, REC_SM>>>(nullptr, w_hh2, nullptr, nullptr, nullptr);

    // GCN
    k_lin1<<<S_ / 8, 128>>>(gcn1_w, gcn1_b);
    k_agg_edge<G1_><<<(E_ * B_ * (G1_ / 4) + 255) / 256, 256>>>(ei);
    k_lin2<<<S_ / 8, 64>>>(gcn2_w, gcn2_b);
    k_agg_edge<G2_><<<(E_ * B_ * (G2_ / 4) + 255) / 256, 256>>>(ei);
    k_final<<<B_, 256>>>(cls_w, cls_b, out);
}